// round 2
// baseline (speedup 1.0000x reference)
#include <cuda_runtime.h>
#include <math.h>

typedef unsigned long long ull;
typedef unsigned int u32;

#define D 512
#define BB 64
#define TOPK 10
#define PARTS 8

#define TN 256
#define KC 32
#define NSTR 33          // spot smem row stride [n][NSTR]
#define NTHREADS 512

// dynamic smem layout (floats):
//   text  : D*BB            = 32768
//   s0    : TN*NSTR         = 8448
//   s1    : TN*NSTR         = 8448
//   psum  : 8*TN            = 2048
//   rnorm : TN              = 256
#define SMEM_FLOATS (D*BB + 2*TN*NSTR + 8*TN + TN)
#define SMEM_BYTES  (SMEM_FLOATS * 4)

// ---------------------------------------------------------------------------
// device scratch (no allocations allowed anywhere)
// ---------------------------------------------------------------------------
__device__ float g_text_t[D * BB];                    // normalized text, [k][b]
__device__ float g_pv[BB * PARTS * TOPK];             // partial top-k values
__device__ int   g_pi[BB * PARTS * TOPK];             // partial top-k indices
__device__ float g_scores_scratch[(size_t)BB * 500000]; // fallback score buffer

// ---------------------------------------------------------------------------
// f32x2 helpers (sm_103a packed fp32 = 2x FFMA throughput)
// ---------------------------------------------------------------------------
__device__ __forceinline__ ull dup2(float s) {
    ull r;
    asm("mov.b64 %0, {%1, %1};" : "=l"(r) : "f"(s));
    return r;
}
__device__ __forceinline__ void ffma2(ull& a, ull x, ull y) {
    asm("fma.rn.f32x2 %0, %1, %2, %0;" : "+l"(a) : "l"(x), "l"(y));
}
__device__ __forceinline__ float2 unpk(ull a) {
    float2 f;
    asm("mov.b64 {%0, %1}, %2;" : "=f"(f.x), "=f"(f.y) : "l"(a));
    return f;
}

// ---------------------------------------------------------------------------
// Kernel 1: normalize text rows -> g_text_t transposed [k][b]
// ---------------------------------------------------------------------------
__global__ void __launch_bounds__(128) k_norm_text(const float* __restrict__ text) {
    const int b = blockIdx.x;
    const int t = threadIdx.x;
    float4 v = ((const float4*)(text + (size_t)b * D))[t];
    float ss = v.x * v.x + v.y * v.y + v.z * v.z + v.w * v.w;
#pragma unroll
    for (int off = 16; off; off >>= 1) ss += __shfl_xor_sync(0xffffffffu, ss, off);
    __shared__ float ws[4];
    if ((t & 31) == 0) ws[t >> 5] = ss;
    __syncthreads();
    float tot = ws[0] + ws[1] + ws[2] + ws[3];
    float scale = 1.0f / fmaxf(sqrtf(tot), 1e-12f);
    const int k = t * 4;
    g_text_t[(k + 0) * BB + b] = v.x * scale;
    g_text_t[(k + 1) * BB + b] = v.y * scale;
    g_text_t[(k + 2) * BB + b] = v.z * scale;
    g_text_t[(k + 3) * BB + b] = v.w * scale;
}

// ---------------------------------------------------------------------------
// Kernel 2: 64 x N x 512 fp32 GEMM + fused spot normalization
// ---------------------------------------------------------------------------
__global__ void __launch_bounds__(NTHREADS) k_gemm(const float* __restrict__ spot,
                                                   float* __restrict__ out,
                                                   int N) {
    extern __shared__ float smem[];
    float* sm_text  = smem;
    float* sm_s[2]  = { sm_text + D * BB, sm_text + D * BB + TN * NSTR };
    float* sm_psum  = sm_text + D * BB + 2 * TN * NSTR;
    float* sm_rnorm = sm_psum + 8 * TN;

    const int t = threadIdx.x;
    const size_t nbase = (size_t)blockIdx.x * TN;

    // stage full normalized text into smem
    {
        const float4* src = (const float4*)g_text_t;
        float4* dst = (float4*)sm_text;
#pragma unroll 4
        for (int i = t; i < D * BB / 4; i += NTHREADS) dst[i] = src[i];
    }

    // loader mapping: kq = k-quad (4 floats), nr = row group (4 rows/thread)
    const int kq = t & 7;
    const int nr = t >> 3;
    // compute mapping: tb = b-group (8 rows), tn = n-group (4 cols)
    const int tb = t & 7;
    const int tn = t >> 3;

    float sq[4] = {0.f, 0.f, 0.f, 0.f};
    float4 stage[4];
    const float4* spot4 = (const float4*)spot;

    // preload + store chunk 0
#pragma unroll
    for (int i = 0; i < 4; i++) {
        size_t ng = nbase + nr + 64 * i;
        if (ng >= (size_t)N) ng = (size_t)N - 1;
        stage[i] = spot4[ng * (D / 4) + kq];
    }
#pragma unroll
    for (int i = 0; i < 4; i++) {
        float4 v = stage[i];
        const int n = nr + 64 * i;
        float* s0 = sm_s[0] + n * NSTR + kq * 4;
        s0[0] = v.x; s0[1] = v.y; s0[2] = v.z; s0[3] = v.w;
        sq[i] += v.x * v.x + v.y * v.y + v.z * v.z + v.w * v.w;
    }
    __syncthreads();

    ull acc[16];
#pragma unroll
    for (int i = 0; i < 16; i++) acc[i] = 0ull;

    for (int c = 0; c < D / KC; ++c) {
        if (c < D / KC - 1) {
#pragma unroll
            for (int i = 0; i < 4; i++) {
                size_t ng = nbase + nr + 64 * i;
                if (ng >= (size_t)N) ng = (size_t)N - 1;
                stage[i] = spot4[ng * (D / 4) + (c + 1) * 8 + kq];
            }
        }
        const float* scur = sm_s[c & 1];
        const float* tbase = sm_text + c * KC * BB + tb * 8;
        const float* sbase = scur + (tn * 4) * NSTR;
#pragma unroll 4
        for (int k = 0; k < KC; ++k) {
            const float* tp = tbase + k * BB;
            ull t0 = *(const ull*)(tp + 0);
            ull t1 = *(const ull*)(tp + 2);
            ull t2 = *(const ull*)(tp + 4);
            ull t3 = *(const ull*)(tp + 6);
            ull d0 = dup2(sbase[0 * NSTR + k]);
            ull d1 = dup2(sbase[1 * NSTR + k]);
            ull d2 = dup2(sbase[2 * NSTR + k]);
            ull d3 = dup2(sbase[3 * NSTR + k]);
            ffma2(acc[0],  t0, d0); ffma2(acc[1],  t1, d0);
            ffma2(acc[2],  t2, d0); ffma2(acc[3],  t3, d0);
            ffma2(acc[4],  t0, d1); ffma2(acc[5],  t1, d1);
            ffma2(acc[6],  t2, d1); ffma2(acc[7],  t3, d1);
            ffma2(acc[8],  t0, d2); ffma2(acc[9],  t1, d2);
            ffma2(acc[10], t2, d2); ffma2(acc[11], t3, d2);
            ffma2(acc[12], t0, d3); ffma2(acc[13], t1, d3);
            ffma2(acc[14], t2, d3); ffma2(acc[15], t3, d3);
        }
        if (c < D / KC - 1) {
            float* snext = sm_s[(c + 1) & 1];
#pragma unroll
            for (int i = 0; i < 4; i++) {
                float4 v = stage[i];
                const int n = nr + 64 * i;
                float* s0 = snext + n * NSTR + kq * 4;
                s0[0] = v.x; s0[1] = v.y; s0[2] = v.z; s0[3] = v.w;
                sq[i] += v.x * v.x + v.y * v.y + v.z * v.z + v.w * v.w;
            }
        }
        __syncthreads();
    }

    // reduce spot squared norms -> rnorm
#pragma unroll
    for (int i = 0; i < 4; i++) sm_psum[kq * TN + nr + 64 * i] = sq[i];
    __syncthreads();
    if (t < TN) {
        float s = 0.f;
#pragma unroll
        for (int q = 0; q < 8; q++) s += sm_psum[q * TN + t];
        sm_rnorm[t] = 1.0f / fmaxf(sqrtf(s), 1e-12f);
    }
    __syncthreads();

    // epilogue: scale by 1/||s|| and store
    const size_t n0 = nbase + tn * 4;
    if (n0 < (size_t)N) {
        float rn0 = sm_rnorm[tn * 4 + 0];
        float rn1 = sm_rnorm[tn * 4 + 1];
        float rn2 = sm_rnorm[tn * 4 + 2];
        float rn3 = sm_rnorm[tn * 4 + 3];
#pragma unroll
        for (int bp = 0; bp < 4; bp++) {
            float2 f0 = unpk(acc[0 * 4 + bp]);
            float2 f1 = unpk(acc[1 * 4 + bp]);
            float2 f2 = unpk(acc[2 * 4 + bp]);
            float2 f3 = unpk(acc[3 * 4 + bp]);
            float4 o0 = make_float4(f0.x * rn0, f1.x * rn1, f2.x * rn2, f3.x * rn3);
            float4 o1 = make_float4(f0.y * rn0, f1.y * rn1, f2.y * rn2, f3.y * rn3);
            const int b = tb * 8 + 2 * bp;
            *(float4*)(out + (size_t)b * N + n0)       = o0;
            *(float4*)(out + (size_t)(b + 1) * N + n0) = o1;
        }
    }
}

// ---------------------------------------------------------------------------
// Kernel 3: partial top-k. grid (PARTS, B), 256 threads
// ---------------------------------------------------------------------------
__device__ __forceinline__ u32 ob(float f) {
    u32 u = __float_as_uint(f);
    return (u & 0x80000000u) ? ~u : (u | 0x80000000u);
}
__device__ __forceinline__ ull packkey(float v, int idx) {
    return ((ull)ob(v) << 32) | (u32)(0xFFFFFFFFu - (u32)idx);
}

__global__ void __launch_bounds__(256) k_topk_partial(const float* __restrict__ scores, int N) {
    const int b = blockIdx.y;
    const int p = blockIdx.x;
    const int t = threadIdx.x;
    const int seg = (N + PARTS - 1) / PARTS;
    const int start = p * seg;
    const int end = min(start + seg, N);

    float v[TOPK];
    int   id[TOPK];
#pragma unroll
    for (int i = 0; i < TOPK; i++) { v[i] = -3.0e38f; id[i] = 0x7fffffff; }
    float vmin = -3.0e38f;

    const float4* row4 = (const float4*)(scores + (size_t)b * N);
    for (int i4 = start / 4 + t; i4 < end / 4; i4 += 256) {
        float4 s4 = row4[i4];
        const int base = i4 * 4;
        float sv[4] = { s4.x, s4.y, s4.z, s4.w };
#pragma unroll
        for (int c = 0; c < 4; c++) {
            float s = sv[c];
            if (s > vmin) {
                int j = TOPK - 1;
                while (j > 0 && s > v[j - 1]) { v[j] = v[j - 1]; id[j] = id[j - 1]; j--; }
                v[j] = s; id[j] = base + c;
                vmin = v[TOPK - 1];
            }
        }
    }

    __shared__ ull red[256];
    int head = 0;
    for (int r = 0; r < TOPK; r++) {
        ull mykey = (head < TOPK) ? packkey(v[head], id[head]) : 0ull;
        red[t] = mykey;
        __syncthreads();
#pragma unroll
        for (int s = 128; s; s >>= 1) {
            if (t < s) { ull o = red[t + s]; if (o > red[t]) red[t] = o; }
            __syncthreads();
        }
        ull win = red[0];
        __syncthreads();
        if (mykey == win && head < TOPK && win != 0ull) {
            g_pv[(b * PARTS + p) * TOPK + r] = v[head];
            g_pi[(b * PARTS + p) * TOPK + r] = id[head];
            head++;
        }
    }
}

// ---------------------------------------------------------------------------
// Kernel 4: merge PARTS*TOPK candidates per row -> final top-k (as float)
// ---------------------------------------------------------------------------
__global__ void __launch_bounds__(32) k_topk_merge(float* __restrict__ out_idx) {
    const int b = blockIdx.x;
    const int lane = threadIdx.x;
    const int NC = PARTS * TOPK; // 80
    ull k0 = packkey(g_pv[b * NC + lane],      g_pi[b * NC + lane]);
    ull k1 = packkey(g_pv[b * NC + lane + 32], g_pi[b * NC + lane + 32]);
    ull k2 = (lane + 64 < NC) ? packkey(g_pv[b * NC + lane + 64], g_pi[b * NC + lane + 64]) : 0ull;

    for (int r = 0; r < TOPK; r++) {
        ull m = k0 > k1 ? k0 : k1;
        if (k2 > m) m = k2;
        ull w = m;
#pragma unroll
        for (int off = 16; off; off >>= 1) {
            ull o = __shfl_xor_sync(0xffffffffu, w, off);
            if (o > w) w = o;
        }
        if (k0 == w) k0 = 0ull;
        else if (k1 == w) k1 = 0ull;
        else if (k2 == w) k2 = 0ull;
        if (lane == 0) {
            int idx = (int)(0xFFFFFFFFu - (u32)w);
            out_idx[b * TOPK + r] = (float)idx;
        }
    }
}

// ---------------------------------------------------------------------------
extern "C" void kernel_launch(void* const* d_in, const int* in_sizes, int n_in,
                              void* d_out, int out_size) {
    const float* text = (const float*)d_in[0];
    const float* spot = (const float*)d_in[1];
    const int N = in_sizes[1] / D;
    float* out = (float*)d_out;

    const long long scores_elems = (long long)BB * N;
    const long long idx_elems = (long long)BB * TOPK;

    float* scores_dst;
    float* idx_dst;
    bool want_topk = true;
    if ((long long)out_size >= scores_elems + idx_elems) {
        scores_dst = out;
        idx_dst = out + scores_elems;
    } else if ((long long)out_size == scores_elems) {
        scores_dst = out;
        idx_dst = nullptr;
        want_topk = false;
    } else {
        // only indices requested: compute scores into device scratch
        void* p = nullptr;
        cudaGetSymbolAddress(&p, g_scores_scratch);
        scores_dst = (float*)p;
        idx_dst = out;
    }

    static bool attr_done = false;
    if (!attr_done) {
        cudaFuncSetAttribute(k_gemm, cudaFuncAttributeMaxDynamicSharedMemorySize, SMEM_BYTES);
        attr_done = true;
    }

    k_norm_text<<<BB, 128>>>(text);
    const int nblk = (N + TN - 1) / TN;
    k_gemm<<<nblk, NTHREADS, SMEM_BYTES>>>(spot, scores_dst, N);
    if (want_topk) {
        k_topk_partial<<<dim3(PARTS, BB), 256>>>(scores_dst, N);
        k_topk_merge<<<BB, 32>>>(idx_dst);
    }
}

// round 3
// speedup vs baseline: 1.1917x; 1.1917x over previous
#include <cuda_runtime.h>
#include <math.h>

typedef unsigned long long ull;
typedef unsigned int u32;

#define D 512
#define BB 64
#define TOPK 10
#define PARTS 8

#define TN 256
#define KC 32
#define NSTR 33          // spot smem row stride in floats
#define NTHREADS 512

// dynamic smem (floats): text 32768 | s0 8448 | s1 8448 | psum 2048 | rnorm 256
#define SMEM_FLOATS (D*BB + 2*TN*NSTR + 8*TN + TN)
#define SMEM_BYTES  (SMEM_FLOATS * 4)

// ---------------------------------------------------------------------------
// device scratch
// ---------------------------------------------------------------------------
// text layout: [k][h][tb][j] with b = tb*8 + h*4 + j  (conflict-free LDS.128)
__device__ float g_text_t[D * BB];
__device__ float g_pv[BB * PARTS * TOPK];
__device__ int   g_pi[BB * PARTS * TOPK];
__device__ float g_scores_scratch[(size_t)BB * 500000];

// ---------------------------------------------------------------------------
// f32x2 helpers (sm_103a packed fp32 = 2x FFMA throughput)
// ---------------------------------------------------------------------------
__device__ __forceinline__ ull dup2(float s) {
    ull r;
    asm("mov.b64 %0, {%1, %1};" : "=l"(r) : "f"(s));
    return r;
}
__device__ __forceinline__ void ffma2(ull& a, ull x, ull y) {
    asm("fma.rn.f32x2 %0, %1, %2, %0;" : "+l"(a) : "l"(x), "l"(y));
}
__device__ __forceinline__ float2 unpk(ull a) {
    float2 f;
    asm("mov.b64 {%0, %1}, %2;" : "=f"(f.x), "=f"(f.y) : "l"(a));
    return f;
}

__global__ void k_nop() {}

// ---------------------------------------------------------------------------
// Kernel 1: normalize text rows -> g_text_t in [k][h][tb][j] layout
// ---------------------------------------------------------------------------
__global__ void __launch_bounds__(128) k_norm_text(const float* __restrict__ text) {
    const int b = blockIdx.x;
    const int t = threadIdx.x;
    float4 v = ((const float4*)(text + (size_t)b * D))[t];
    float ss = v.x * v.x + v.y * v.y + v.z * v.z + v.w * v.w;
#pragma unroll
    for (int off = 16; off; off >>= 1) ss += __shfl_xor_sync(0xffffffffu, ss, off);
    __shared__ float ws[4];
    if ((t & 31) == 0) ws[t >> 5] = ss;
    __syncthreads();
    float tot = ws[0] + ws[1] + ws[2] + ws[3];
    float scale = 1.0f / fmaxf(sqrtf(tot), 1e-12f);
    const int tb = b >> 3;
    const int h  = (b >> 2) & 1;
    const int j  = b & 3;
    const int boff = h * 32 + tb * 4 + j;
    const int k = t * 4;
    g_text_t[(k + 0) * BB + boff] = v.x * scale;
    g_text_t[(k + 1) * BB + boff] = v.y * scale;
    g_text_t[(k + 2) * BB + boff] = v.z * scale;
    g_text_t[(k + 3) * BB + boff] = v.w * scale;
}

// ---------------------------------------------------------------------------
// Kernel 2: 64 x N x 512 fp32 GEMM + fused spot normalization
// ---------------------------------------------------------------------------
__global__ void __launch_bounds__(NTHREADS, 1) k_gemm(const float* __restrict__ spot,
                                                      float* __restrict__ out,
                                                      int N) {
    extern __shared__ float smem[];
    float* sm_text  = smem;
    float* sm_s[2]  = { sm_text + D * BB, sm_text + D * BB + TN * NSTR };
    float* sm_psum  = sm_text + D * BB + 2 * TN * NSTR;
    float* sm_rnorm = sm_psum + 8 * TN;

    const int t = threadIdx.x;
    const size_t nbase = (size_t)blockIdx.x * TN;

    // stage full normalized text into smem (layout already conflict-free)
    {
        const float4* src = (const float4*)g_text_t;
        float4* dst = (float4*)sm_text;
#pragma unroll 4
        for (int i = t; i < D * BB / 4; i += NTHREADS) dst[i] = src[i];
    }

    const int kq = t & 7;        // loader: k-quad
    const int nr = t >> 3;       // loader: row (4 rows per thread, stride 64)
    const int tb = t & 7;        // compute: b-group of 8
    const int tn = t >> 3;       // compute: n-group of 4

    float sq[4] = {0.f, 0.f, 0.f, 0.f};
    float4 stage[4];
    const float4* spot4 = (const float4*)spot;

#pragma unroll
    for (int i = 0; i < 4; i++) {
        size_t ng = nbase + nr + 64 * i;
        if (ng >= (size_t)N) ng = (size_t)N - 1;
        stage[i] = spot4[ng * (D / 4) + kq];
    }
#pragma unroll
    for (int i = 0; i < 4; i++) {
        float4 v = stage[i];
        float* s0 = sm_s[0] + (nr + 64 * i) * NSTR + kq * 4;
        s0[0] = v.x; s0[1] = v.y; s0[2] = v.z; s0[3] = v.w;
        sq[i] = fmaf(v.x, v.x, fmaf(v.y, v.y, fmaf(v.z, v.z, fmaf(v.w, v.w, sq[i]))));
    }
    __syncthreads();

    ull acc[16];
#pragma unroll
    for (int i = 0; i < 16; i++) acc[i] = 0ull;

    for (int c = 0; c < D / KC; ++c) {
        if (c < D / KC - 1) {
#pragma unroll
            for (int i = 0; i < 4; i++) {
                size_t ng = nbase + nr + 64 * i;
                if (ng >= (size_t)N) ng = (size_t)N - 1;
                stage[i] = spot4[ng * (D / 4) + (c + 1) * 8 + kq];
            }
        }
        const float* scur = sm_s[c & 1];
        const float* tbase = sm_text + c * KC * BB + tb * 4;   // [k][h][tb][4]
        const float* sbase = scur + (tn * 4) * NSTR;
#pragma unroll 4
        for (int k = 0; k < KC; ++k) {
            // text: 2x LDS.128, conflict-free (banks 4*tb..4*tb+3)
            ulonglong2 T0 = *(const ulonglong2*)(tbase + k * BB);       // b: tb*8+0..3
            ulonglong2 T1 = *(const ulonglong2*)(tbase + k * BB + 32);  // b: tb*8+4..7
            ull d0 = dup2(sbase[0 * NSTR + k]);
            ull d1 = dup2(sbase[1 * NSTR + k]);
            ull d2 = dup2(sbase[2 * NSTR + k]);
            ull d3 = dup2(sbase[3 * NSTR + k]);
            ffma2(acc[0],  T0.x, d0); ffma2(acc[1],  T0.y, d0);
            ffma2(acc[2],  T1.x, d0); ffma2(acc[3],  T1.y, d0);
            ffma2(acc[4],  T0.x, d1); ffma2(acc[5],  T0.y, d1);
            ffma2(acc[6],  T1.x, d1); ffma2(acc[7],  T1.y, d1);
            ffma2(acc[8],  T0.x, d2); ffma2(acc[9],  T0.y, d2);
            ffma2(acc[10], T1.x, d2); ffma2(acc[11], T1.y, d2);
            ffma2(acc[12], T0.x, d3); ffma2(acc[13], T0.y, d3);
            ffma2(acc[14], T1.x, d3); ffma2(acc[15], T1.y, d3);
        }
        if (c < D / KC - 1) {
            float* snext = sm_s[(c + 1) & 1];
#pragma unroll
            for (int i = 0; i < 4; i++) {
                float4 v = stage[i];
                float* s0 = snext + (nr + 64 * i) * NSTR + kq * 4;
                s0[0] = v.x; s0[1] = v.y; s0[2] = v.z; s0[3] = v.w;
                sq[i] = fmaf(v.x, v.x, fmaf(v.y, v.y, fmaf(v.z, v.z, fmaf(v.w, v.w, sq[i]))));
            }
        }
        __syncthreads();
    }

    // reduce spot squared norms
#pragma unroll
    for (int i = 0; i < 4; i++) sm_psum[kq * TN + nr + 64 * i] = sq[i];
    __syncthreads();
    if (t < TN) {
        float s = 0.f;
#pragma unroll
        for (int q = 0; q < 8; q++) s += sm_psum[q * TN + t];
        sm_rnorm[t] = 1.0f / fmaxf(sqrtf(s), 1e-12f);
    }
    __syncthreads();

    // epilogue
    const size_t n0 = nbase + tn * 4;
    if (n0 < (size_t)N) {
        float rn0 = sm_rnorm[tn * 4 + 0];
        float rn1 = sm_rnorm[tn * 4 + 1];
        float rn2 = sm_rnorm[tn * 4 + 2];
        float rn3 = sm_rnorm[tn * 4 + 3];
#pragma unroll
        for (int bp = 0; bp < 4; bp++) {
            float2 f0 = unpk(acc[0 * 4 + bp]);
            float2 f1 = unpk(acc[1 * 4 + bp]);
            float2 f2 = unpk(acc[2 * 4 + bp]);
            float2 f3 = unpk(acc[3 * 4 + bp]);
            float4 o0 = make_float4(f0.x * rn0, f1.x * rn1, f2.x * rn2, f3.x * rn3);
            float4 o1 = make_float4(f0.y * rn0, f1.y * rn1, f2.y * rn2, f3.y * rn3);
            const int b = tb * 8 + 2 * bp;
            *(float4*)(out + (size_t)b * N + n0)       = o0;
            *(float4*)(out + (size_t)(b + 1) * N + n0) = o1;
        }
    }
}

// ---------------------------------------------------------------------------
// Kernel 3: partial top-k. grid (PARTS, B), 256 threads
// ---------------------------------------------------------------------------
__device__ __forceinline__ u32 ob(float f) {
    u32 u = __float_as_uint(f);
    return (u & 0x80000000u) ? ~u : (u | 0x80000000u);
}
__device__ __forceinline__ ull packkey(float v, int idx) {
    return ((ull)ob(v) << 32) | (u32)(0xFFFFFFFFu - (u32)idx);
}

__global__ void __launch_bounds__(256) k_topk_partial(const float* __restrict__ scores, int N) {
    const int b = blockIdx.y;
    const int p = blockIdx.x;
    const int t = threadIdx.x;
    const int seg = (N + PARTS - 1) / PARTS;
    const int start = p * seg;
    const int end = min(start + seg, N);

    float v[TOPK];
    int   id[TOPK];
#pragma unroll
    for (int i = 0; i < TOPK; i++) { v[i] = -3.0e38f; id[i] = 0x7fffffff; }
    float vmin = -3.0e38f;

    const float4* row4 = (const float4*)(scores + (size_t)b * N);
    for (int i4 = start / 4 + t; i4 < end / 4; i4 += 256) {
        float4 s4 = row4[i4];
        const int base = i4 * 4;
        float sv[4] = { s4.x, s4.y, s4.z, s4.w };
#pragma unroll
        for (int c = 0; c < 4; c++) {
            float s = sv[c];
            if (s > vmin) {
                int j = TOPK - 1;
                while (j > 0 && s > v[j - 1]) { v[j] = v[j - 1]; id[j] = id[j - 1]; j--; }
                v[j] = s; id[j] = base + c;
                vmin = v[TOPK - 1];
            }
        }
    }

    __shared__ ull red[256];
    int head = 0;
    for (int r = 0; r < TOPK; r++) {
        ull mykey = (head < TOPK) ? packkey(v[head], id[head]) : 0ull;
        red[t] = mykey;
        __syncthreads();
#pragma unroll
        for (int s = 128; s; s >>= 1) {
            if (t < s) { ull o = red[t + s]; if (o > red[t]) red[t] = o; }
            __syncthreads();
        }
        ull win = red[0];
        __syncthreads();
        if (mykey == win && head < TOPK && win != 0ull) {
            g_pv[(b * PARTS + p) * TOPK + r] = v[head];
            g_pi[(b * PARTS + p) * TOPK + r] = id[head];
            head++;
        }
    }
}

// ---------------------------------------------------------------------------
// Kernel 4: merge PARTS*TOPK candidates per row -> final indices (as float)
// ---------------------------------------------------------------------------
__global__ void __launch_bounds__(32) k_topk_merge(float* __restrict__ out_idx) {
    const int b = blockIdx.x;
    const int lane = threadIdx.x;
    const int NC = PARTS * TOPK; // 80
    ull k0 = packkey(g_pv[b * NC + lane],      g_pi[b * NC + lane]);
    ull k1 = packkey(g_pv[b * NC + lane + 32], g_pi[b * NC + lane + 32]);
    ull k2 = (lane + 64 < NC) ? packkey(g_pv[b * NC + lane + 64], g_pi[b * NC + lane + 64]) : 0ull;

    for (int r = 0; r < TOPK; r++) {
        ull m = k0 > k1 ? k0 : k1;
        if (k2 > m) m = k2;
        ull w = m;
#pragma unroll
        for (int off = 16; off; off >>= 1) {
            ull o = __shfl_xor_sync(0xffffffffu, w, off);
            if (o > w) w = o;
        }
        if (k0 == w) k0 = 0ull;
        else if (k1 == w) k1 = 0ull;
        else if (k2 == w) k2 = 0ull;
        if (lane == 0) {
            int idx = (int)(0xFFFFFFFFu - (u32)w);
            out_idx[b * TOPK + r] = (float)idx;
        }
    }
}

// ---------------------------------------------------------------------------
extern "C" void kernel_launch(void* const* d_in, const int* in_sizes, int n_in,
                              void* d_out, int out_size) {
    const float* text = (const float*)d_in[0];
    const float* spot = (const float*)d_in[1];
    const int N = in_sizes[1] / D;
    float* out = (float*)d_out;

    const long long scores_elems = (long long)BB * N;
    const long long idx_elems = (long long)BB * TOPK;

    float* scores_dst;
    float* idx_dst = nullptr;
    bool want_topk = true;
    if ((long long)out_size >= scores_elems + idx_elems) {
        scores_dst = out;
        idx_dst = out + scores_elems;
    } else if ((long long)out_size == scores_elems) {
        scores_dst = out;
        want_topk = false;
    } else {
        void* p = nullptr;
        cudaGetSymbolAddress(&p, g_scores_scratch);
        scores_dst = (float*)p;
        idx_dst = out;
    }

    cudaFuncSetAttribute(k_gemm, cudaFuncAttributeMaxDynamicSharedMemorySize, SMEM_BYTES);

    // profiler-alignment nops (shift ncu -s 5 capture onto k_gemm)
    k_nop<<<1, 32>>>();
    k_nop<<<1, 32>>>();

    k_norm_text<<<BB, 128>>>(text);
    const int nblk = (N + TN - 1) / TN;
    k_gemm<<<nblk, NTHREADS, SMEM_BYTES>>>(spot, scores_dst, N);
    if (want_topk) {
        k_topk_partial<<<dim3(PARTS, BB), 256>>>(scores_dst, N);
        k_topk_merge<<<BB, 32>>>(idx_dst);
    }
}

// round 4
// speedup vs baseline: 1.3532x; 1.1355x over previous
#include <cuda_runtime.h>
#include <math.h>

typedef unsigned long long ull;
typedef unsigned int u32;

#define D 512
#define BB 64
#define TOPK 10
#define PARTS 8

#define TN 256
#define KC 32
#define NCHUNK (D / KC)     // 16
#define NTHREADS 512

// smem floats: text 32768 | spot(dup) 16384 | psum 2048 | rnorm 256
#define SM_SPOT  (D * BB)
#define SM_PSUM  (SM_SPOT + KC * 2 * TN)
#define SM_RNORM (SM_PSUM + 8 * TN)
#define SMEM_FLOATS (SM_RNORM + TN)
#define SMEM_BYTES  (SMEM_FLOATS * 4)

// ---------------------------------------------------------------------------
// device scratch
// ---------------------------------------------------------------------------
// text layout: [k][b'] with b' = h*32 + tb*4 + j, b = tb*8 + h*4 + j
__device__ float g_text_t[D * BB];
__device__ float g_pv[BB * PARTS * TOPK];
__device__ int   g_pi[BB * PARTS * TOPK];
__device__ float g_scores_scratch[(size_t)BB * 500000];

// ---------------------------------------------------------------------------
// f32x2 helpers
// ---------------------------------------------------------------------------
__device__ __forceinline__ void ffma2(ull& a, ull x, ull y) {
    asm("fma.rn.f32x2 %0, %1, %2, %0;" : "+l"(a) : "l"(x), "l"(y));
}
__device__ __forceinline__ float2 unpk(ull a) {
    float2 f;
    asm("mov.b64 {%0, %1}, %2;" : "=f"(f.x), "=f"(f.y) : "l"(a));
    return f;
}

__global__ void k_nop() {}

// ---------------------------------------------------------------------------
// Kernel 1: normalize text rows -> g_text_t [k][b'] layout
// ---------------------------------------------------------------------------
__global__ void __launch_bounds__(128) k_norm_text(const float* __restrict__ text) {
    const int b = blockIdx.x;
    const int t = threadIdx.x;
    float4 v = ((const float4*)(text + (size_t)b * D))[t];
    float ss = v.x * v.x + v.y * v.y + v.z * v.z + v.w * v.w;
#pragma unroll
    for (int off = 16; off; off >>= 1) ss += __shfl_xor_sync(0xffffffffu, ss, off);
    __shared__ float ws[4];
    if ((t & 31) == 0) ws[t >> 5] = ss;
    __syncthreads();
    float tot = ws[0] + ws[1] + ws[2] + ws[3];
    float scale = 1.0f / fmaxf(sqrtf(tot), 1e-12f);
    const int tb = b >> 3;
    const int h  = (b >> 2) & 1;
    const int j  = b & 3;
    const int boff = h * 32 + tb * 4 + j;
    const int k = t * 4;
    g_text_t[(k + 0) * BB + boff] = v.x * scale;
    g_text_t[(k + 1) * BB + boff] = v.y * scale;
    g_text_t[(k + 2) * BB + boff] = v.z * scale;
    g_text_t[(k + 3) * BB + boff] = v.w * scale;
}

// ---------------------------------------------------------------------------
// Kernel 2: 64 x N x 512 fp32 GEMM + fused spot normalization
//   spot smem: [k][2*TN] pre-duplicated, 16B units XOR-swizzled by (k>>2)&7
// ---------------------------------------------------------------------------
__global__ void __launch_bounds__(NTHREADS, 1) k_gemm(const float* __restrict__ spot,
                                                      float* __restrict__ out,
                                                      int N) {
    extern __shared__ float smem[];
    float* sm_text  = smem;
    float* sm_spot  = smem + SM_SPOT;
    float* sm_psum  = smem + SM_PSUM;
    float* sm_rnorm = smem + SM_RNORM;

    const int t = threadIdx.x;
    const size_t nbase = (size_t)blockIdx.x * TN;

    // stage normalized text into smem
    {
        const float4* src = (const float4*)g_text_t;
        float4* dst = (float4*)sm_text;
#pragma unroll 4
        for (int i = t; i < D * BB / 4; i += NTHREADS) dst[i] = src[i];
    }

    const int kq = t & 7;   // loader: float4 index along k (k_local = kq*4+j)
    const int nr = t >> 3;  // loader: base row (rows nr + 64*i)
    const int tb = t & 7;   // compute: b-group of 8
    const int tn = t >> 3;  // compute: n-group of 4

    float sq[4] = {0.f, 0.f, 0.f, 0.f};
    float4 stage[4];
    const float4* spot4 = (const float4*)spot;

    size_t ng[4];
#pragma unroll
    for (int i = 0; i < 4; i++) {
        size_t v = nbase + nr + 64 * i;
        ng[i] = (v < (size_t)N) ? v : (size_t)N - 1;
    }

    // preload + store chunk 0 (duplicated + swizzled)
#pragma unroll
    for (int i = 0; i < 4; i++) stage[i] = spot4[ng[i] * (D / 4) + kq];
#pragma unroll
    for (int i = 0; i < 4; i++) {
        const int n = nr + 64 * i;
        const int boff = (((n >> 1) ^ kq) << 2) + ((n & 1) << 1);
        float vv[4] = { stage[i].x, stage[i].y, stage[i].z, stage[i].w };
#pragma unroll
        for (int j = 0; j < 4; j++) {
            *(float2*)(sm_spot + (kq * 4 + j) * (2 * TN) + boff) = make_float2(vv[j], vv[j]);
        }
        sq[i] = fmaf(vv[0], vv[0], fmaf(vv[1], vv[1], fmaf(vv[2], vv[2], fmaf(vv[3], vv[3], sq[i]))));
    }
    __syncthreads();

    ull acc[16];
#pragma unroll
    for (int i = 0; i < 16; i++) acc[i] = 0ull;

    for (int c = 0; c < NCHUNK; ++c) {
        if (c + 1 < NCHUNK) {
#pragma unroll
            for (int i = 0; i < 4; i++) stage[i] = spot4[ng[i] * (D / 4) + (c + 1) * 8 + kq];
        }
        const float* tbase = sm_text + c * KC * BB + tb * 4;
#pragma unroll
        for (int k = 0; k < KC; ++k) {
            ulonglong2 T0 = *(const ulonglong2*)(tbase + k * BB);        // b: 0..3
            ulonglong2 T1 = *(const ulonglong2*)(tbase + k * BB + 32);   // b: 4..7
            const int g = (k >> 2) & 7;
            const float* sp = sm_spot + k * (2 * TN);
            ulonglong2 S0 = *(const ulonglong2*)(sp + ((((2 * tn)     ^ g)) << 2)); // dup n0,n1
            ulonglong2 S1 = *(const ulonglong2*)(sp + ((((2 * tn + 1) ^ g)) << 2)); // dup n2,n3
            ffma2(acc[0],  T0.x, S0.x); ffma2(acc[1],  T0.y, S0.x);
            ffma2(acc[2],  T1.x, S0.x); ffma2(acc[3],  T1.y, S0.x);
            ffma2(acc[4],  T0.x, S0.y); ffma2(acc[5],  T0.y, S0.y);
            ffma2(acc[6],  T1.x, S0.y); ffma2(acc[7],  T1.y, S0.y);
            ffma2(acc[8],  T0.x, S1.x); ffma2(acc[9],  T0.y, S1.x);
            ffma2(acc[10], T1.x, S1.x); ffma2(acc[11], T1.y, S1.x);
            ffma2(acc[12], T0.x, S1.y); ffma2(acc[13], T0.y, S1.y);
            ffma2(acc[14], T1.x, S1.y); ffma2(acc[15], T1.y, S1.y);
        }
        __syncthreads();
        if (c + 1 < NCHUNK) {
#pragma unroll
            for (int i = 0; i < 4; i++) {
                const int n = nr + 64 * i;
                const int boff = (((n >> 1) ^ kq) << 2) + ((n & 1) << 1);
                float vv[4] = { stage[i].x, stage[i].y, stage[i].z, stage[i].w };
#pragma unroll
                for (int j = 0; j < 4; j++) {
                    *(float2*)(sm_spot + (kq * 4 + j) * (2 * TN) + boff) = make_float2(vv[j], vv[j]);
                }
                sq[i] = fmaf(vv[0], vv[0], fmaf(vv[1], vv[1], fmaf(vv[2], vv[2], fmaf(vv[3], vv[3], sq[i]))));
            }
            __syncthreads();
        }
    }

    // reduce spot squared norms -> rnorm
#pragma unroll
    for (int i = 0; i < 4; i++) sm_psum[kq * TN + nr + 64 * i] = sq[i];
    __syncthreads();
    if (t < TN) {
        float s = 0.f;
#pragma unroll
        for (int q = 0; q < 8; q++) s += sm_psum[q * TN + t];
        sm_rnorm[t] = 1.0f / fmaxf(sqrtf(s), 1e-12f);
    }
    __syncthreads();

    // epilogue: acc[n*4+bp] pairs along b (b = tb*8 + 2*bp)
    const size_t n0 = nbase + tn * 4;
    if (n0 < (size_t)N) {
        float rn0 = sm_rnorm[tn * 4 + 0];
        float rn1 = sm_rnorm[tn * 4 + 1];
        float rn2 = sm_rnorm[tn * 4 + 2];
        float rn3 = sm_rnorm[tn * 4 + 3];
#pragma unroll
        for (int bp = 0; bp < 4; bp++) {
            float2 f0 = unpk(acc[0 * 4 + bp]);
            float2 f1 = unpk(acc[1 * 4 + bp]);
            float2 f2 = unpk(acc[2 * 4 + bp]);
            float2 f3 = unpk(acc[3 * 4 + bp]);
            float4 o0 = make_float4(f0.x * rn0, f1.x * rn1, f2.x * rn2, f3.x * rn3);
            float4 o1 = make_float4(f0.y * rn0, f1.y * rn1, f2.y * rn2, f3.y * rn3);
            const int b = tb * 8 + 2 * bp;
            *(float4*)(out + (size_t)b * N + n0)       = o0;
            *(float4*)(out + (size_t)(b + 1) * N + n0) = o1;
        }
    }
}

// ---------------------------------------------------------------------------
// Kernel 3: partial top-k
// ---------------------------------------------------------------------------
__device__ __forceinline__ u32 ob(float f) {
    u32 u = __float_as_uint(f);
    return (u & 0x80000000u) ? ~u : (u | 0x80000000u);
}
__device__ __forceinline__ ull packkey(float v, int idx) {
    return ((ull)ob(v) << 32) | (u32)(0xFFFFFFFFu - (u32)idx);
}

__global__ void __launch_bounds__(256) k_topk_partial(const float* __restrict__ scores, int N) {
    const int b = blockIdx.y;
    const int p = blockIdx.x;
    const int t = threadIdx.x;
    const int seg = (N + PARTS - 1) / PARTS;
    const int start = p * seg;
    const int end = min(start + seg, N);

    float v[TOPK];
    int   id[TOPK];
#pragma unroll
    for (int i = 0; i < TOPK; i++) { v[i] = -3.0e38f; id[i] = 0x7fffffff; }
    float vmin = -3.0e38f;

    const float4* row4 = (const float4*)(scores + (size_t)b * N);
    for (int i4 = start / 4 + t; i4 < end / 4; i4 += 256) {
        float4 s4 = row4[i4];
        const int base = i4 * 4;
        float sv[4] = { s4.x, s4.y, s4.z, s4.w };
#pragma unroll
        for (int c = 0; c < 4; c++) {
            float s = sv[c];
            if (s > vmin) {
                int j = TOPK - 1;
                while (j > 0 && s > v[j - 1]) { v[j] = v[j - 1]; id[j] = id[j - 1]; j--; }
                v[j] = s; id[j] = base + c;
                vmin = v[TOPK - 1];
            }
        }
    }

    __shared__ ull red[256];
    int head = 0;
    for (int r = 0; r < TOPK; r++) {
        ull mykey = (head < TOPK) ? packkey(v[head], id[head]) : 0ull;
        red[t] = mykey;
        __syncthreads();
#pragma unroll
        for (int s = 128; s; s >>= 1) {
            if (t < s) { ull o = red[t + s]; if (o > red[t]) red[t] = o; }
            __syncthreads();
        }
        ull win = red[0];
        __syncthreads();
        if (mykey == win && head < TOPK && win != 0ull) {
            g_pv[(b * PARTS + p) * TOPK + r] = v[head];
            g_pi[(b * PARTS + p) * TOPK + r] = id[head];
            head++;
        }
    }
}

// ---------------------------------------------------------------------------
// Kernel 4: final merge
// ---------------------------------------------------------------------------
__global__ void __launch_bounds__(32) k_topk_merge(float* __restrict__ out_idx) {
    const int b = blockIdx.x;
    const int lane = threadIdx.x;
    const int NC = PARTS * TOPK; // 80
    ull k0 = packkey(g_pv[b * NC + lane],      g_pi[b * NC + lane]);
    ull k1 = packkey(g_pv[b * NC + lane + 32], g_pi[b * NC + lane + 32]);
    ull k2 = (lane + 64 < NC) ? packkey(g_pv[b * NC + lane + 64], g_pi[b * NC + lane + 64]) : 0ull;

    for (int r = 0; r < TOPK; r++) {
        ull m = k0 > k1 ? k0 : k1;
        if (k2 > m) m = k2;
        ull w = m;
#pragma unroll
        for (int off = 16; off; off >>= 1) {
            ull o = __shfl_xor_sync(0xffffffffu, w, off);
            if (o > w) w = o;
        }
        if (k0 == w) k0 = 0ull;
        else if (k1 == w) k1 = 0ull;
        else if (k2 == w) k2 = 0ull;
        if (lane == 0) {
            int idx = (int)(0xFFFFFFFFu - (u32)w);
            out_idx[b * TOPK + r] = (float)idx;
        }
    }
}

// ---------------------------------------------------------------------------
extern "C" void kernel_launch(void* const* d_in, const int* in_sizes, int n_in,
                              void* d_out, int out_size) {
    const float* text = (const float*)d_in[0];
    const float* spot = (const float*)d_in[1];
    const int N = in_sizes[1] / D;
    float* out = (float*)d_out;

    const long long scores_elems = (long long)BB * N;
    const long long idx_elems = (long long)BB * TOPK;

    float* scores_dst;
    float* idx_dst = nullptr;
    bool want_topk = true;
    if ((long long)out_size >= scores_elems + idx_elems) {
        scores_dst = out;
        idx_dst = out + scores_elems;
    } else if ((long long)out_size == scores_elems) {
        scores_dst = out;
        want_topk = false;
    } else {
        void* p = nullptr;
        cudaGetSymbolAddress(&p, g_scores_scratch);
        scores_dst = (float*)p;
        idx_dst = out;
    }

    cudaFuncSetAttribute(k_gemm, cudaFuncAttributeMaxDynamicSharedMemorySize, SMEM_BYTES);

    // profiler-alignment nops (keep ncu -s 5 on k_gemm)
    k_nop<<<1, 32>>>();
    k_nop<<<1, 32>>>();

    k_norm_text<<<BB, 128>>>(text);
    const int nblk = (N + TN - 1) / TN;
    k_gemm<<<nblk, NTHREADS, SMEM_BYTES>>>(spot, scores_dst, N);
    if (want_topk) {
        k_topk_partial<<<dim3(PARTS, BB), 256>>>(scores_dst, N);
        k_topk_merge<<<BB, 32>>>(idx_dst);
    }
}

// round 5
// speedup vs baseline: 1.9033x; 1.4065x over previous
#include <cuda_runtime.h>
#include <math.h>

typedef unsigned long long ull;
typedef unsigned int u32;

#define D 512
#define BB 64
#define TOPK 10
#define PARTS 8

#define TN 384            // n per CTA
#define KC 16             // k chunk
#define NCHUNK (D / KC)   // 32
#define NTHREADS 256

// smem floats: text 32768 | spot KC*TN=6144 | psum 4*TN=1536 | rnorm TN
#define SM_SPOT  (D * BB)
#define SM_PSUM  (SM_SPOT + KC * TN)
#define SM_RNORM (SM_PSUM + 4 * TN)
#define SMEM_FLOATS (SM_RNORM + TN)
#define SMEM_BYTES  (SMEM_FLOATS * 4)

// ---------------------------------------------------------------------------
// device scratch
// ---------------------------------------------------------------------------
// text layout: [k][b'] with b' = h*32 + tb*4 + j, b = tb*8 + h*4 + j
__device__ float g_text_t[D * BB];
__device__ float g_pv[BB * PARTS * TOPK];
__device__ int   g_pi[BB * PARTS * TOPK];
__device__ float g_scores_scratch[(size_t)BB * 500000];

// ---------------------------------------------------------------------------
// f32x2 helpers
// ---------------------------------------------------------------------------
__device__ __forceinline__ ull dup2(float s) {
    ull r;
    asm("mov.b64 %0, {%1, %1};" : "=l"(r) : "f"(s));
    return r;
}
__device__ __forceinline__ void ffma2(ull& a, ull x, ull y) {
    asm("fma.rn.f32x2 %0, %1, %2, %0;" : "+l"(a) : "l"(x), "l"(y));
}
__device__ __forceinline__ float2 unpk(ull a) {
    float2 f;
    asm("mov.b64 {%0, %1}, %2;" : "=f"(f.x), "=f"(f.y) : "l"(a));
    return f;
}

__global__ void k_nop() {}

// ---------------------------------------------------------------------------
// Kernel 1: normalize text rows -> g_text_t [k][b'] layout
// ---------------------------------------------------------------------------
__global__ void __launch_bounds__(128) k_norm_text(const float* __restrict__ text) {
    const int b = blockIdx.x;
    const int t = threadIdx.x;
    float4 v = ((const float4*)(text + (size_t)b * D))[t];
    float ss = v.x * v.x + v.y * v.y + v.z * v.z + v.w * v.w;
#pragma unroll
    for (int off = 16; off; off >>= 1) ss += __shfl_xor_sync(0xffffffffu, ss, off);
    __shared__ float ws[4];
    if ((t & 31) == 0) ws[t >> 5] = ss;
    __syncthreads();
    float tot = ws[0] + ws[1] + ws[2] + ws[3];
    float scale = 1.0f / fmaxf(sqrtf(tot), 1e-12f);
    const int tb = b >> 3;
    const int h  = (b >> 2) & 1;
    const int j  = b & 3;
    const int boff = h * 32 + tb * 4 + j;
    const int k = t * 4;
    g_text_t[(k + 0) * BB + boff] = v.x * scale;
    g_text_t[(k + 1) * BB + boff] = v.y * scale;
    g_text_t[(k + 2) * BB + boff] = v.z * scale;
    g_text_t[(k + 3) * BB + boff] = v.w * scale;
}

// ---------------------------------------------------------------------------
// Kernel 2: 64 x N x 512 fp32 GEMM + fused spot normalization
//   256 threads, thread tile 8b x 12n, acc packed along n.
//   spot smem: [k][96 units of 16B], unit swizzle U = (n>>2) ^ ((k>>2)&3)
// ---------------------------------------------------------------------------
__global__ void __launch_bounds__(NTHREADS, 1) k_gemm(const float* __restrict__ spot,
                                                      float* __restrict__ out,
                                                      int N) {
    extern __shared__ float smem[];
    float* sm_text  = smem;
    float* sm_spot  = smem + SM_SPOT;
    float* sm_psum  = smem + SM_PSUM;
    float* sm_rnorm = smem + SM_RNORM;

    const int t = threadIdx.x;
    const size_t nbase = (size_t)blockIdx.x * TN;

    // stage normalized text into smem
    {
        const float4* src = (const float4*)g_text_t;
        float4* dst = (float4*)sm_text;
#pragma unroll 8
        for (int i = t; i < D * BB / 4; i += NTHREADS) dst[i] = src[i];
    }

    // loader mapping: cq = float4-col within 64B row-chunk, r = base row
    const int cq = t & 3;
    const int r  = t >> 2;        // 0..63; rows r + 64*i, i=0..5
    // compute mapping
    const int tb = t & 7;         // b-group of 8
    const int tn = t >> 3;        // n-group of 12 (0..31)

    const float4* spot4 = (const float4*)spot;
    size_t ng[6];
#pragma unroll
    for (int i = 0; i < 6; i++) {
        size_t v = nbase + r + 64 * i;
        ng[i] = (v < (size_t)N) ? v : (size_t)N - 1;
    }

    float sq[6] = {0.f, 0.f, 0.f, 0.f, 0.f, 0.f};
    float4 stage[6];

    // preload + store chunk 0
#pragma unroll
    for (int i = 0; i < 6; i++) stage[i] = spot4[ng[i] * (D / 4) + cq];
#pragma unroll
    for (int i = 0; i < 6; i++) {
        const int n = r + 64 * i;
        float vv[4] = { stage[i].x, stage[i].y, stage[i].z, stage[i].w };
#pragma unroll
        for (int j = 0; j < 4; j++) {
            const int k = cq * 4 + j;
            const int U = (n >> 2) ^ ((k >> 2) & 3);
            sm_spot[k * TN + U * 4 + (n & 3)] = vv[j];
        }
        sq[i] = fmaf(vv[0], vv[0], fmaf(vv[1], vv[1], fmaf(vv[2], vv[2], fmaf(vv[3], vv[3], sq[i]))));
    }
    __syncthreads();

    ull acc[48];   // acc[bi*6 + np]: b = tb*8+bi, n = tn*12 + 2*np (+1)
#pragma unroll
    for (int i = 0; i < 48; i++) acc[i] = 0ull;

    for (int c = 0; c < NCHUNK; ++c) {
        if (c + 1 < NCHUNK) {
#pragma unroll
            for (int i = 0; i < 6; i++)
                stage[i] = spot4[ng[i] * (D / 4) + (c + 1) * 4 + cq];
        }
        const float* tb4 = sm_text + c * KC * BB + tb * 4;
#pragma unroll
        for (int kk = 0; kk < KC; ++kk) {
            const float4 T0 = *(const float4*)(tb4 + kk * BB);        // b: +0..3
            const float4 T1 = *(const float4*)(tb4 + kk * BB + 32);   // b: +4..7
            const int f = (kk >> 2) & 3;
            const float* sp = sm_spot + kk * TN;
            ulonglong2 S0 = *(const ulonglong2*)(sp + ((((3 * tn + 0) ^ f)) << 2));
            ulonglong2 S1 = *(const ulonglong2*)(sp + ((((3 * tn + 1) ^ f)) << 2));
            ulonglong2 S2 = *(const ulonglong2*)(sp + ((((3 * tn + 2) ^ f)) << 2));
            ull a[8];
            a[0] = dup2(T0.x); a[1] = dup2(T0.y); a[2] = dup2(T0.z); a[3] = dup2(T0.w);
            a[4] = dup2(T1.x); a[5] = dup2(T1.y); a[6] = dup2(T1.z); a[7] = dup2(T1.w);
#pragma unroll
            for (int bi = 0; bi < 8; bi++) {
                ffma2(acc[bi * 6 + 0], a[bi], S0.x);
                ffma2(acc[bi * 6 + 1], a[bi], S0.y);
                ffma2(acc[bi * 6 + 2], a[bi], S1.x);
                ffma2(acc[bi * 6 + 3], a[bi], S1.y);
                ffma2(acc[bi * 6 + 4], a[bi], S2.x);
                ffma2(acc[bi * 6 + 5], a[bi], S2.y);
            }
        }
        __syncthreads();
        if (c + 1 < NCHUNK) {
#pragma unroll
            for (int i = 0; i < 6; i++) {
                const int n = r + 64 * i;
                float vv[4] = { stage[i].x, stage[i].y, stage[i].z, stage[i].w };
#pragma unroll
                for (int j = 0; j < 4; j++) {
                    const int k = cq * 4 + j;
                    const int U = (n >> 2) ^ ((k >> 2) & 3);
                    sm_spot[k * TN + U * 4 + (n & 3)] = vv[j];
                }
                sq[i] = fmaf(vv[0], vv[0], fmaf(vv[1], vv[1], fmaf(vv[2], vv[2], fmaf(vv[3], vv[3], sq[i]))));
            }
            __syncthreads();
        }
    }

    // spot norm reduction
#pragma unroll
    for (int i = 0; i < 6; i++) sm_psum[cq * TN + r + 64 * i] = sq[i];
    __syncthreads();
    for (int row = t; row < TN; row += NTHREADS) {
        float s = sm_psum[row] + sm_psum[TN + row] + sm_psum[2 * TN + row] + sm_psum[3 * TN + row];
        sm_rnorm[row] = 1.0f / fmaxf(sqrtf(s), 1e-12f);
    }
    __syncthreads();

    // epilogue
    const int n0 = tn * 12;
    const size_t gn0 = nbase + n0;
    float rn[12];
#pragma unroll
    for (int j = 0; j < 12; j++) rn[j] = sm_rnorm[n0 + j];
#pragma unroll
    for (int bi = 0; bi < 8; bi++) {
        const size_t b = (size_t)(tb * 8 + bi);
        float fo[12];
#pragma unroll
        for (int np = 0; np < 6; np++) {
            float2 p = unpk(acc[bi * 6 + np]);
            fo[2 * np]     = p.x * rn[2 * np];
            fo[2 * np + 1] = p.y * rn[2 * np + 1];
        }
#pragma unroll
        for (int u = 0; u < 3; u++) {
            if (gn0 + 4 * u < (size_t)N) {
                *(float4*)(out + b * N + gn0 + 4 * u) =
                    make_float4(fo[4 * u], fo[4 * u + 1], fo[4 * u + 2], fo[4 * u + 3]);
            }
        }
    }
}

// ---------------------------------------------------------------------------
// Kernel 3: partial top-k (register-resident static compare-swap chain)
// ---------------------------------------------------------------------------
__device__ __forceinline__ u32 ob(float f) {
    u32 u = __float_as_uint(f);
    return (u & 0x80000000u) ? ~u : (u | 0x80000000u);
}
__device__ __forceinline__ ull packkey(float v, int idx) {
    return ((ull)ob(v) << 32) | (u32)(0xFFFFFFFFu - (u32)idx);
}

__global__ void __launch_bounds__(256) k_topk_partial(const float* __restrict__ scores, int N) {
    const int b = blockIdx.y;
    const int p = blockIdx.x;
    const int t = threadIdx.x;
    const int seg = (N + PARTS - 1) / PARTS;
    const int start = p * seg;
    const int end = min(start + seg, N);

    float v[TOPK];
    int   id[TOPK];
#pragma unroll
    for (int i = 0; i < TOPK; i++) { v[i] = -3.0e38f; id[i] = 0x7fffffff; }
    float vmin = -3.0e38f;

    const float4* row4 = (const float4*)(scores + (size_t)b * N);
    for (int i4 = start / 4 + t; i4 < end / 4; i4 += 256) {
        float4 s4 = row4[i4];
        const int base = i4 * 4;
        float sv[4] = { s4.x, s4.y, s4.z, s4.w };
#pragma unroll
        for (int c = 0; c < 4; c++) {
            float s = sv[c];
            if (s > vmin) {
                float cv = s; int ci = base + c;
#pragma unroll
                for (int j = 0; j < TOPK; j++) {
                    if (cv > v[j]) {
                        float tv = v[j]; v[j] = cv; cv = tv;
                        int   ti = id[j]; id[j] = ci; ci = ti;
                    }
                }
                vmin = v[TOPK - 1];
            }
        }
    }

    __shared__ ull red[256];
    int head = 0;
    for (int rdd = 0; rdd < TOPK; rdd++) {
        ull mykey = (head < TOPK) ? packkey(v[head], id[head]) : 0ull;
        red[t] = mykey;
        __syncthreads();
#pragma unroll
        for (int s = 128; s; s >>= 1) {
            if (t < s) { ull o = red[t + s]; if (o > red[t]) red[t] = o; }
            __syncthreads();
        }
        ull win = red[0];
        __syncthreads();
        if (mykey == win && head < TOPK && win != 0ull) {
            g_pv[(b * PARTS + p) * TOPK + rdd] = v[head];
            g_pi[(b * PARTS + p) * TOPK + rdd] = id[head];
            head++;
        }
    }
}

// ---------------------------------------------------------------------------
// Kernel 4: final merge
// ---------------------------------------------------------------------------
__global__ void __launch_bounds__(32) k_topk_merge(float* __restrict__ out_idx) {
    const int b = blockIdx.x;
    const int lane = threadIdx.x;
    const int NC = PARTS * TOPK; // 80
    ull k0 = packkey(g_pv[b * NC + lane],      g_pi[b * NC + lane]);
    ull k1 = packkey(g_pv[b * NC + lane + 32], g_pi[b * NC + lane + 32]);
    ull k2 = (lane + 64 < NC) ? packkey(g_pv[b * NC + lane + 64], g_pi[b * NC + lane + 64]) : 0ull;

    for (int rd = 0; rd < TOPK; rd++) {
        ull m = k0 > k1 ? k0 : k1;
        if (k2 > m) m = k2;
        ull w = m;
#pragma unroll
        for (int off = 16; off; off >>= 1) {
            ull o = __shfl_xor_sync(0xffffffffu, w, off);
            if (o > w) w = o;
        }
        if (k0 == w) k0 = 0ull;
        else if (k1 == w) k1 = 0ull;
        else if (k2 == w) k2 = 0ull;
        if (lane == 0) {
            int idx = (int)(0xFFFFFFFFu - (u32)w);
            out_idx[b * TOPK + rd] = (float)idx;
        }
    }
}

// ---------------------------------------------------------------------------
extern "C" void kernel_launch(void* const* d_in, const int* in_sizes, int n_in,
                              void* d_out, int out_size) {
    const float* text = (const float*)d_in[0];
    const float* spot = (const float*)d_in[1];
    const int N = in_sizes[1] / D;
    float* out = (float*)d_out;

    const long long scores_elems = (long long)BB * N;
    const long long idx_elems = (long long)BB * TOPK;

    float* scores_dst;
    float* idx_dst = nullptr;
    bool want_topk = true;
    if ((long long)out_size >= scores_elems + idx_elems) {
        scores_dst = out;
        idx_dst = out + scores_elems;
    } else if ((long long)out_size == scores_elems) {
        scores_dst = out;
        want_topk = false;
    } else {
        void* p = nullptr;
        cudaGetSymbolAddress(&p, g_scores_scratch);
        scores_dst = (float*)p;
        idx_dst = out;
    }

    cudaFuncSetAttribute(k_gemm, cudaFuncAttributeMaxDynamicSharedMemorySize, SMEM_BYTES);

    // profiler-alignment nops (keep ncu -s 5 on k_gemm)
    k_nop<<<1, 32>>>();
    k_nop<<<1, 32>>>();

    k_norm_text<<<BB, 128>>>(text);
    const int nblk = (N + TN - 1) / TN;
    k_gemm<<<nblk, NTHREADS, SMEM_BYTES>>>(spot, scores_dst, N);
    if (want_topk) {
        k_topk_partial<<<dim3(PARTS, BB), 256>>>(scores_dst, N);
        k_topk_merge<<<BB, 32>>>(idx_dst);
    }
}

// round 7
// speedup vs baseline: 3.4457x; 1.8104x over previous
#include <cuda_runtime.h>
#include <cuda_bf16.h>
#include <math.h>

typedef unsigned long long ull;
typedef unsigned int u32;

#define D 512
#define BB 64
#define TOPK 10
#define PARTS 8

#define TM 128             // spots per CTA tile
#define KC 32              // k per chunk
#define NCH (D / KC)       // 16
#define GTH 256

// per-stage smem (bytes): AH 8192 | AL 8192 | BH 4096 | BL 4096
#define STG_BYTES 24576
#define OFF_AH 0
#define OFF_AL 8192
#define OFF_BH 16384
#define OFF_BL 20480
#define OFF_RN (2 * STG_BYTES)          // 49152
#define SMEM_BYTES (OFF_RN + 512)       // 49664

// ---------------------------------------------------------------------------
// device scratch
// ---------------------------------------------------------------------------
__device__ __align__(16) __nv_bfloat16 g_Bh[BB * D];  // normalized text hi [b][k]
__device__ __align__(16) __nv_bfloat16 g_Bl[BB * D];  // residual lo
__device__ float g_pv[BB * PARTS * TOPK];
__device__ int   g_pi[BB * PARTS * TOPK];
__device__ float g_scores_scratch[(size_t)BB * 500000];

// ---------------------------------------------------------------------------
// helpers
// ---------------------------------------------------------------------------
__device__ __forceinline__ u32 s2u(const void* p) {
    u32 a;
    asm("{ .reg .u64 t; cvta.to.shared.u64 t, %1; cvt.u32.u64 %0, t; }"
        : "=r"(a) : "l"(p));
    return a;
}
// pack two floats -> bf16x2 word, e0 in LOW half (first k), e1 in HIGH half
__device__ __forceinline__ u32 pack2(float e0, float e1) {
    u32 r;
    asm("cvt.rn.bf16x2.f32 %0, %1, %2;" : "=r"(r) : "f"(e1), "f"(e0));
    return r;
}
__device__ __forceinline__ float bflo(u32 p) { return __uint_as_float(p << 16); }
__device__ __forceinline__ float bfhi(u32 p) { return __uint_as_float(p & 0xffff0000u); }

// SW128-style swizzle for bf16 tiles with 64B logical rows (row pairs share a
// 128B line). row: tile row, k: bf16 column (0..31). Returns byte offset.
__device__ __forceinline__ u32 swz(u32 row, u32 k) {
    u32 line = row >> 1;
    u32 u = ((row & 1) << 2) | (k >> 3);
    return line * 128 + ((u ^ (line & 7)) << 4) + ((k & 7) << 1);
}

#define LDSM4(R, A) \
    asm volatile("ldmatrix.sync.aligned.m8n8.x4.shared.b16 {%0,%1,%2,%3}, [%4];" \
                 : "=r"((R)[0]), "=r"((R)[1]), "=r"((R)[2]), "=r"((R)[3]) : "r"(A))

__device__ __forceinline__ void bmma(float* c, const u32* a, u32 b0, u32 b1) {
    asm("mma.sync.aligned.m16n8k16.row.col.f32.bf16.bf16.f32 "
        "{%0,%1,%2,%3}, {%4,%5,%6,%7}, {%8,%9}, {%0,%1,%2,%3};"
        : "+f"(c[0]), "+f"(c[1]), "+f"(c[2]), "+f"(c[3])
        : "r"(a[0]), "r"(a[1]), "r"(a[2]), "r"(a[3]), "r"(b0), "r"(b1));
}

__global__ void k_nop() {}

// ---------------------------------------------------------------------------
// Kernel 1: normalize text rows, split to bf16 hi/lo in global
// ---------------------------------------------------------------------------
__global__ void __launch_bounds__(128) k_prep_text(const float* __restrict__ text) {
    const int b = blockIdx.x;
    const int t = threadIdx.x;
    float4 v = ((const float4*)(text + (size_t)b * D))[t];
    float ss = v.x * v.x + v.y * v.y + v.z * v.z + v.w * v.w;
#pragma unroll
    for (int off = 16; off; off >>= 1) ss += __shfl_xor_sync(0xffffffffu, ss, off);
    __shared__ float ws[4];
    if ((t & 31) == 0) ws[t >> 5] = ss;
    __syncthreads();
    float tot = ws[0] + ws[1] + ws[2] + ws[3];
    float scale = 1.0f / fmaxf(sqrtf(tot), 1e-12f);
    float nv[4] = { v.x * scale, v.y * scale, v.z * scale, v.w * scale };
    const int k = t * 4;
#pragma unroll
    for (int i = 0; i < 4; i++) {
        __nv_bfloat16 h = __float2bfloat16(nv[i]);
        float hf = __bfloat162float(h);
        __nv_bfloat16 l = __float2bfloat16(nv[i] - hf);
        g_Bh[b * D + k + i] = h;
        g_Bl[b * D + k + i] = l;
    }
}

// ---------------------------------------------------------------------------
// Kernel 2: 3x-bf16 mma.sync GEMM. CTA: 128 spots x 64 texts x K=512.
// ---------------------------------------------------------------------------
__global__ void __launch_bounds__(GTH, 2)
k_gemm_mma(const float* __restrict__ spot, float* __restrict__ out, int N) {
    extern __shared__ char smem[];
    const u32 sb = s2u(smem);
    const int t = threadIdx.x;
    const int lane = t & 31, warp = t >> 5;
    const size_t tile = blockIdx.x;

    // A loader: 2 threads per spot row (64B halves)
    const int ra = t >> 1, ha = t & 1;
    size_t rowg = tile * TM + ra;
    if (rowg >= (size_t)N) rowg = (size_t)N - 1;
    const float4* arow = (const float4*)(spot + rowg * D);
    // B loader: 4 threads per text row (16B units)
    const int nB = t >> 2, ksB = t & 3;
    const uint4* bhrow = (const uint4*)(g_Bh + (size_t)nB * D);
    const uint4* blrow = (const uint4*)(g_Bl + (size_t)nB * D);

    // compute mapping: warp tile 32m x 32n
    const int m0 = (warp >> 1) * 32;
    const int n0 = (warp & 1) * 32;
    const int rowA = ((lane >> 3) & 1) * 8 + (lane & 7);
    const int kA   = (lane >> 4) * 8;
    const int rowB = ((lane >> 4) & 1) * 8 + (lane & 7);
    const int kB   = ((lane >> 3) & 1) * 8;

    float c[2][4][4];
#pragma unroll
    for (int i = 0; i < 2; i++)
#pragma unroll
        for (int j = 0; j < 4; j++)
#pragma unroll
            for (int q = 0; q < 4; q++) c[i][j][q] = 0.f;

    float sq = 0.f;
    float4 va[4];
    uint4 vbh, vbl;

    auto lda = [&](int cc) {
#pragma unroll
        for (int i = 0; i < 4; i++) va[i] = arow[cc * 8 + ha * 4 + i];
        vbh = bhrow[cc * 4 + ksB];
        vbl = blrow[cc * 4 + ksB];
    };
    auto sts = [&](int s) {
        char* base = smem + s * STG_BYTES;
        u32 hw[8], lw[8];
#pragma unroll
        for (int i = 0; i < 4; i++) {
            float4 v = va[i];
            u32 h0 = pack2(v.x, v.y), h1 = pack2(v.z, v.w);
            u32 l0 = pack2(v.x - bflo(h0), v.y - bfhi(h0));
            u32 l1 = pack2(v.z - bflo(h1), v.w - bfhi(h1));
            hw[2 * i] = h0; hw[2 * i + 1] = h1;
            lw[2 * i] = l0; lw[2 * i + 1] = l1;
            sq = fmaf(v.x, v.x, fmaf(v.y, v.y, fmaf(v.z, v.z, fmaf(v.w, v.w, sq))));
        }
        *(uint4*)(base + OFF_AH + swz(ra, ha * 16))     = make_uint4(hw[0], hw[1], hw[2], hw[3]);
        *(uint4*)(base + OFF_AH + swz(ra, ha * 16 + 8)) = make_uint4(hw[4], hw[5], hw[6], hw[7]);
        *(uint4*)(base + OFF_AL + swz(ra, ha * 16))     = make_uint4(lw[0], lw[1], lw[2], lw[3]);
        *(uint4*)(base + OFF_AL + swz(ra, ha * 16 + 8)) = make_uint4(lw[4], lw[5], lw[6], lw[7]);
        *(uint4*)(base + OFF_BH + swz(nB, ksB * 8)) = vbh;
        *(uint4*)(base + OFF_BL + swz(nB, ksB * 8)) = vbl;
    };
    auto domma = [&](int s) {
        const u32 ab = sb + s * STG_BYTES;
#pragma unroll
        for (int kst = 0; kst < 2; kst++) {
            const int k0 = kst * 16;
            u32 ah[2][4], al[2][4], bh2[2][4], bl2[2][4];
#pragma unroll
            for (int mt = 0; mt < 2; mt++) {
                LDSM4(ah[mt], ab + OFF_AH + swz(m0 + mt * 16 + rowA, kA + k0));
                LDSM4(al[mt], ab + OFF_AL + swz(m0 + mt * 16 + rowA, kA + k0));
            }
#pragma unroll
            for (int jt = 0; jt < 2; jt++) {
                LDSM4(bh2[jt], ab + OFF_BH + swz(n0 + jt * 16 + rowB, kB + k0));
                LDSM4(bl2[jt], ab + OFF_BL + swz(n0 + jt * 16 + rowB, kB + k0));
            }
#pragma unroll
            for (int mt = 0; mt < 2; mt++)
#pragma unroll
                for (int nt = 0; nt < 4; nt++) {
                    const u32* bh_ = &bh2[nt >> 1][(nt & 1) * 2];
                    const u32* bl_ = &bl2[nt >> 1][(nt & 1) * 2];
                    bmma(c[mt][nt], ah[mt], bh_[0], bh_[1]);
                    bmma(c[mt][nt], ah[mt], bl_[0], bl_[1]);
                    bmma(c[mt][nt], al[mt], bh_[0], bh_[1]);
                }
        }
    };

    lda(0);
    sts(0);
    __syncthreads();
    for (int cc = 0; cc < NCH; cc++) {
        if (cc < NCH - 1) lda(cc + 1);
        domma(cc & 1);
        if (cc < NCH - 1) {
            __syncthreads();
            sts((cc + 1) & 1);
            __syncthreads();
        }
    }

    // spot norms
    float s2 = sq + __shfl_xor_sync(0xffffffffu, sq, 1);
    float* rnorm = (float*)(smem + OFF_RN);
    if (ha == 0) rnorm[ra] = 1.0f / fmaxf(sqrtf(s2), 1e-12f);
    __syncthreads();

    // epilogue
    const int ml = lane >> 2, nl = (lane & 3) * 2;
#pragma unroll
    for (int mt = 0; mt < 2; mt++) {
        const int mloc = m0 + mt * 16 + ml;
        const size_t gm = tile * TM + mloc;
        const float rn0 = rnorm[mloc];
        const float rn8 = rnorm[mloc + 8];
#pragma unroll
        for (int nt = 0; nt < 4; nt++) {
            const int ng = n0 + nt * 8 + nl;
            if (gm < (size_t)N) {
                out[(size_t)ng * N + gm]       = c[mt][nt][0] * rn0;
                out[(size_t)(ng + 1) * N + gm] = c[mt][nt][1] * rn0;
            }
            if (gm + 8 < (size_t)N) {
                out[(size_t)ng * N + gm + 8]       = c[mt][nt][2] * rn8;
                out[(size_t)(ng + 1) * N + gm + 8] = c[mt][nt][3] * rn8;
            }
        }
    }
}

// ---------------------------------------------------------------------------
// Kernel 3: partial top-k
// ---------------------------------------------------------------------------
__device__ __forceinline__ u32 ob(float f) {
    u32 u = __float_as_uint(f);
    return (u & 0x80000000u) ? ~u : (u | 0x80000000u);
}
__device__ __forceinline__ ull packkey(float v, int idx) {
    return ((ull)ob(v) << 32) | (u32)(0xFFFFFFFFu - (u32)idx);
}

__global__ void __launch_bounds__(256) k_topk_partial(const float* __restrict__ scores, int N) {
    const int b = blockIdx.y;
    const int p = blockIdx.x;
    const int t = threadIdx.x;
    const int seg = (N + PARTS - 1) / PARTS;
    const int start = p * seg;
    const int end = min(start + seg, N);

    float v[TOPK];
    int   id[TOPK];
#pragma unroll
    for (int i = 0; i < TOPK; i++) { v[i] = -3.0e38f; id[i] = 0x7fffffff; }
    float vmin = -3.0e38f;

    const float4* row4 = (const float4*)(scores + (size_t)b * N);
    for (int i4 = start / 4 + t; i4 < end / 4; i4 += 256) {
        float4 s4 = row4[i4];
        const int base = i4 * 4;
        float sv[4] = { s4.x, s4.y, s4.z, s4.w };
#pragma unroll
        for (int cc = 0; cc < 4; cc++) {
            float s = sv[cc];
            if (s > vmin) {
                float cv = s; int ci = base + cc;
#pragma unroll
                for (int j = 0; j < TOPK; j++) {
                    if (cv > v[j]) {
                        float tv = v[j]; v[j] = cv; cv = tv;
                        int   ti = id[j]; id[j] = ci; ci = ti;
                    }
                }
                vmin = v[TOPK - 1];
            }
        }
    }

    __shared__ ull red[256];
    int head = 0;
    for (int rdd = 0; rdd < TOPK; rdd++) {
        ull mykey = (head < TOPK) ? packkey(v[head], id[head]) : 0ull;
        red[t] = mykey;
        __syncthreads();
#pragma unroll
        for (int s = 128; s; s >>= 1) {
            if (t < s) { ull o = red[t + s]; if (o > red[t]) red[t] = o; }
            __syncthreads();
        }
        ull win = red[0];
        __syncthreads();
        if (mykey == win && head < TOPK && win != 0ull) {
            g_pv[(b * PARTS + p) * TOPK + rdd] = v[head];
            g_pi[(b * PARTS + p) * TOPK + rdd] = id[head];
            head++;
        }
    }
}

// ---------------------------------------------------------------------------
// Kernel 4: final merge
// ---------------------------------------------------------------------------
__global__ void __launch_bounds__(32) k_topk_merge(float* __restrict__ out_idx) {
    const int b = blockIdx.x;
    const int lane = threadIdx.x;
    const int NC = PARTS * TOPK; // 80
    ull k0 = packkey(g_pv[b * NC + lane],      g_pi[b * NC + lane]);
    ull k1 = packkey(g_pv[b * NC + lane + 32], g_pi[b * NC + lane + 32]);
    ull k2 = (lane + 64 < NC) ? packkey(g_pv[b * NC + lane + 64], g_pi[b * NC + lane + 64]) : 0ull;

    for (int rd = 0; rd < TOPK; rd++) {
        ull m = k0 > k1 ? k0 : k1;
        if (k2 > m) m = k2;
        ull w = m;
#pragma unroll
        for (int off = 16; off; off >>= 1) {
            ull o = __shfl_xor_sync(0xffffffffu, w, off);
            if (o > w) w = o;
        }
        if (k0 == w) k0 = 0ull;
        else if (k1 == w) k1 = 0ull;
        else if (k2 == w) k2 = 0ull;
        if (lane == 0) {
            int idx = (int)(0xFFFFFFFFu - (u32)w);
            out_idx[b * TOPK + rd] = (float)idx;
        }
    }
}

// ---------------------------------------------------------------------------
extern "C" void kernel_launch(void* const* d_in, const int* in_sizes, int n_in,
                              void* d_out, int out_size) {
    const float* text = (const float*)d_in[0];
    const float* spot = (const float*)d_in[1];
    const int N = in_sizes[1] / D;
    float* out = (float*)d_out;

    const long long scores_elems = (long long)BB * N;
    const long long idx_elems = (long long)BB * TOPK;

    float* scores_dst;
    float* idx_dst = nullptr;
    bool want_topk = true;
    if ((long long)out_size >= scores_elems + idx_elems) {
        scores_dst = out;
        idx_dst = out + scores_elems;
    } else if ((long long)out_size == scores_elems) {
        scores_dst = out;
        want_topk = false;
    } else {
        void* p = nullptr;
        cudaGetSymbolAddress(&p, g_scores_scratch);
        scores_dst = (float*)p;
        idx_dst = out;
    }

    cudaFuncSetAttribute(k_gemm_mma, cudaFuncAttributeMaxDynamicSharedMemorySize, SMEM_BYTES);

    // profiler-alignment nops (keep ncu -s 5 on the gemm)
    k_nop<<<1, 32>>>();
    k_nop<<<1, 32>>>();

    k_prep_text<<<BB, 128>>>(text);
    const int ntile = (N + TM - 1) / TM;
    k_gemm_mma<<<ntile, GTH, SMEM_BYTES>>>(spot, scores_dst, N);
    if (want_topk) {
        k_topk_partial<<<dim3(PARTS, BB), 256>>>(scores_dst, N);
        k_topk_merge<<<BB, 32>>>(idx_dst);
    }
}